// round 7
// baseline (speedup 1.0000x reference)
#include <cuda_runtime.h>
#include <cuda_fp16.h>
#include <cstdint>
#include <math.h>

// Problem constants
#define BB   2
#define SS   2048
#define DIN  2048
#define NH   8
#define NKV  4
#define HD   256
#define QDIM  (NH*HD)    // 2048
#define KVDIM (NKV*HD)   // 1024
#define FUSED 4096       // q(2048) | k(1024) | v(1024)
#define SCALING 0.0625f
#define EPS 1e-6f

// ---------------------------------------------------------------------------
// Scratch (device globals)
// ---------------------------------------------------------------------------
__device__ float  g_qkv [(size_t)BB*SS*FUSED];   // fp32 pre-norm qkv
__device__ __half g_qkvh[(size_t)BB*SS*FUSED];   // fp16 post-norm/rope qkv
__device__ __half g_xh  [(size_t)BB*SS*DIN];
__device__ __half g_wf  [(size_t)FUSED*DIN];     // fused wq|wk|wv fp16
__device__ __half g_woh [(size_t)DIN*QDIM];
__device__ __half g_ch  [(size_t)BB*SS*QDIM];

// ---------------------------------------------------------------------------
// Helpers
// ---------------------------------------------------------------------------
__device__ __forceinline__ uint32_t smem_to_u32(const void* smem_ptr) {
    uint32_t addr;
    asm("{ .reg .u64 tmp; cvta.to.shared.u64 tmp, %1; cvt.u32.u64 %0, tmp; }"
        : "=r"(addr) : "l"(smem_ptr));
    return addr;
}
__device__ __forceinline__ void ldsm_x4(uint32_t* r, uint32_t addr) {
    asm volatile("ldmatrix.sync.aligned.m8n8.x4.shared.b16 {%0,%1,%2,%3}, [%4];"
                 : "=r"(r[0]), "=r"(r[1]), "=r"(r[2]), "=r"(r[3]) : "r"(addr));
}
__device__ __forceinline__ void ldsm_x4t(uint32_t* r, uint32_t addr) {
    asm volatile("ldmatrix.sync.aligned.m8n8.x4.trans.shared.b16 {%0,%1,%2,%3}, [%4];"
                 : "=r"(r[0]), "=r"(r[1]), "=r"(r[2]), "=r"(r[3]) : "r"(addr));
}
__device__ __forceinline__ void mma_f16(float* d, const uint32_t* a, const uint32_t* b) {
    asm volatile(
        "mma.sync.aligned.m16n8k16.row.col.f32.f16.f16.f32 "
        "{%0,%1,%2,%3}, {%4,%5,%6,%7}, {%8,%9}, {%0,%1,%2,%3};"
        : "+f"(d[0]), "+f"(d[1]), "+f"(d[2]), "+f"(d[3])
        : "r"(a[0]), "r"(a[1]), "r"(a[2]), "r"(a[3]), "r"(b[0]), "r"(b[1]));
}
__device__ __forceinline__ void cp_async16(uint32_t dst, const void* src) {
    asm volatile("cp.async.cg.shared.global [%0], [%1], 16;" :: "r"(dst), "l"(src));
}
__device__ __forceinline__ uint32_t pack_h2(float x0, float x1) {
    __half2 h = __floats2half2_rn(x0, x1);
    return *(uint32_t*)&h;
}

// fp32 -> fp16 convert, vectorized by 4
__global__ void cvt_f16(const float* __restrict__ x, __half* __restrict__ out, int n4) {
    int i = blockIdx.x * blockDim.x + threadIdx.x;
    if (i >= n4) return;
    float4 v = ((const float4*)x)[i];
    uint2 r;
    r.x = pack_h2(v.x, v.y);
    r.y = pack_h2(v.z, v.w);
    ((uint2*)out)[i] = r;
}

// ---------------------------------------------------------------------------
// HMMA GEMM v2 (NT, fp16): C[M,N] = A[M,K] @ B[N,K]^T.
// CTA tile 128x256, BK=32, 8 warps (2x4), warp tile 64x64, 3-stage cp.async,
// one __syncthreads per chunk.
// ---------------------------------------------------------------------------
#define GBM 128
#define GBN 256
#define GBK 32
#define GPITCH 80
#define GA_BYTES (GBM * GPITCH)          // 10240
#define GB_BYTES (GBN * GPITCH)          // 20480
#define GSTAGE  (GA_BYTES + GB_BYTES)    // 30720
#define GSMEM   (3 * GSTAGE)             // 92160

__global__ __launch_bounds__(256, 1)
void gemm_f16(const __half* __restrict__ A, const __half* __restrict__ B,
              float* __restrict__ C, int M, int N, int K) {
    extern __shared__ char smemc[];
    const uint32_t smem = smem_to_u32(smemc);
    const int tid = threadIdx.x;
    const int wid = tid >> 5;
    const int lid = tid & 31;
    const int warp_m = wid & 1;     // 0-1
    const int warp_n = wid >> 1;    // 0-3
    const int m0 = blockIdx.y * GBM;
    const int n0 = blockIdx.x * GBN;
    const int kchunks = K / GBK;

#define PREFETCH(cc) do {                                                     \
        const int s_ = (cc) % 3;                                              \
        const int k0_ = (cc) * GBK;                                           \
        _Pragma("unroll")                                                     \
        for (int it = 0; it < 6; it++) {                                      \
            int g = tid + 256 * it;                                           \
            if (g < 512) {                                                    \
                int r = g >> 2, q = g & 3;                                    \
                cp_async16(smem + s_ * GSTAGE + r * GPITCH + q * 16,          \
                           A + (size_t)(m0 + r) * K + k0_ + q * 8);           \
            } else {                                                          \
                int gb = g - 512;                                             \
                int r = gb >> 2, q = gb & 3;                                  \
                cp_async16(smem + s_ * GSTAGE + GA_BYTES + r * GPITCH + q * 16, \
                           B + (size_t)(n0 + r) * K + k0_ + q * 8);           \
            }                                                                 \
        }                                                                     \
        asm volatile("cp.async.commit_group;");                               \
    } while (0)

    float acc[4][8][4];
#pragma unroll
    for (int i = 0; i < 4; i++)
#pragma unroll
        for (int j = 0; j < 8; j++)
#pragma unroll
            for (int q = 0; q < 4; q++) acc[i][j][q] = 0.f;

    PREFETCH(0);
    PREFETCH(1);

    for (int c = 0; c < kchunks; c++) {
        if (c + 1 < kchunks) {
            asm volatile("cp.async.wait_group 1;" ::: "memory");
        } else {
            asm volatile("cp.async.wait_group 0;" ::: "memory");
        }
        __syncthreads();
        if (c + 2 < kchunks) PREFETCH(c + 2);   // writes stage consumed 2 iters ago

        const uint32_t sA = smem + (c % 3) * GSTAGE;
        const uint32_t sB = sA + GA_BYTES;

#pragma unroll
        for (int k16 = 0; k16 < 2; k16++) {
            const int coff = k16 * 16;
            uint32_t a[4][4];
            {
                int ra = warp_m * 64 + (lid & 15);
                int ka = coff + (lid >> 4) * 8;
#pragma unroll
                for (int i = 0; i < 4; i++)
                    ldsm_x4(a[i], sA + (uint32_t)((ra + i * 16) * GPITCH + ka * 2));
            }
            uint32_t bb[4][4];
            {
                int rb = warp_n * 64 + ((lid >> 4) << 3) + (lid & 7);
                int kb = coff + ((lid >> 3) & 1) * 8;
#pragma unroll
                for (int j = 0; j < 4; j++)
                    ldsm_x4(bb[j], sB + (uint32_t)((rb + j * 16) * GPITCH + kb * 2));
            }
#pragma unroll
            for (int i = 0; i < 4; i++)
#pragma unroll
                for (int jj = 0; jj < 8; jj++)
                    mma_f16(acc[i][jj], a[i], &bb[jj >> 1][(jj & 1) * 2]);
        }
    }

    const int rbase = m0 + warp_m * 64 + (lid >> 2);
    const int cbase = n0 + warp_n * 64 + (lid & 3) * 2;
#pragma unroll
    for (int i = 0; i < 4; i++)
#pragma unroll
        for (int jj = 0; jj < 8; jj++) {
            float* p0 = C + (size_t)(rbase + i * 16) * N + cbase + jj * 8;
            float* p1 = C + (size_t)(rbase + i * 16 + 8) * N + cbase + jj * 8;
            *(float2*)p0 = make_float2(acc[i][jj][0], acc[i][jj][1]);
            *(float2*)p1 = make_float2(acc[i][jj][2], acc[i][jj][3]);
        }
#undef PREFETCH
}

// ---------------------------------------------------------------------------
// RMSNorm + RoPE v2: warp-per-head, strided 8 elems/lane (RoPE partner is
// same-lane). heads 0-7: q (norm+rope+scale), 8-11: k (norm+rope),
// 12-15: v (convert only). grid (M, 2), block 256.
// ---------------------------------------------------------------------------
__global__ void rms_rope2(const float* __restrict__ cosp,
                          const float* __restrict__ sinp,
                          const float* __restrict__ qg,
                          const float* __restrict__ kg) {
    const int bs = blockIdx.x;
    const int spos = bs & (SS - 1);
    const int wid = threadIdx.x >> 5, lane = threadIdx.x & 31;
    const int head = blockIdx.y * 8 + wid;   // 0..15

    int col0;
    if (head < 8)       col0 = head * HD;
    else if (head < 12) col0 = 2048 + (head - 8) * HD;
    else                col0 = 3072 + (head - 12) * HD;

    const float* src = g_qkv + (size_t)bs * FUSED + col0;
    __half* dst = g_qkvh + (size_t)bs * FUSED + col0;

    float v[8];
#pragma unroll
    for (int i = 0; i < 8; i++) v[i] = src[lane + 32 * i];

    if (head < 12) {
        float ssum = 0.f;
#pragma unroll
        for (int i = 0; i < 8; i++) ssum += v[i] * v[i];
#pragma unroll
        for (int off = 16; off >= 1; off >>= 1)
            ssum += __shfl_xor_sync(0xffffffffu, ssum, off);
        float rstd = rsqrtf(ssum * (1.0f / HD) + EPS);
        const float* gamma = (head < 8) ? qg : kg;
        float scale = (head < 8) ? SCALING : 1.0f;
        float xn[8];
#pragma unroll
        for (int i = 0; i < 8; i++)
            xn[i] = v[i] * rstd * (1.0f + gamma[lane + 32 * i]);
#pragma unroll
        for (int i = 0; i < 8; i++) {
            int d = lane + 32 * i;
            float rot = (i < 4) ? -xn[i + 4] : xn[i - 4];
            float o = (xn[i] * cosp[(size_t)spos * HD + d]
                     + rot * sinp[(size_t)spos * HD + d]) * scale;
            dst[d] = __float2half(o);
        }
    } else {
#pragma unroll
        for (int i = 0; i < 8; i++)
            dst[lane + 32 * i] = __float2half(v[i]);
    }
}

// ---------------------------------------------------------------------------
// Flash attention v2, fp16 HMMA. BM=128, BN=64, D=256, 256 threads (8 warps,
// warp owns 16 q-rows). Longest CTAs launched first (qb descending).
// ---------------------------------------------------------------------------
#define FPITCH 528
#define FQTILE (128 * FPITCH)               // 67584
#define FKTILE (64 * FPITCH)                // 33792
#define FSMEM_BYTES (FQTILE + 2 * FKTILE)   // 135168

__global__ __launch_bounds__(256)
void flash_f16(const __half* __restrict__ qh, const __half* __restrict__ kh,
               const __half* __restrict__ vh, __half* __restrict__ ch) {
    extern __shared__ char smemc[];
    const uint32_t smem = smem_to_u32(smemc);
    const uint32_t sQ = smem;
    const uint32_t sK = smem + FQTILE;
    const uint32_t sV = smem + FQTILE + FKTILE;

    const int qb = (int)gridDim.x - 1 - (int)blockIdx.x;  // long CTAs first
    const int h = blockIdx.y, b = blockIdx.z;
    const int kvh = h >> 1;
    const int tid = threadIdx.x, wid = tid >> 5, lid = tid & 31;
    const int q0 = qb * 128;
    const int ktmax = 2 * qb + 1;

    // Q tile: 128 rows
#pragma unroll
    for (int it = 0; it < 16; it++) {
        int g = tid + 256 * it;
        int row = g >> 5, c16 = g & 31;
        size_t go = (size_t)(b * SS + q0 + row) * FUSED + h * HD + c16 * 8;
        cp_async16(sQ + row * FPITCH + c16 * 16, qh + go);
    }
    asm volatile("cp.async.commit_group;");

#define LOAD_KV(dst, src, row0) do {                                          \
        _Pragma("unroll")                                                     \
        for (int it = 0; it < 8; it++) {                                      \
            int g = tid + 256 * it;                                           \
            int row = g >> 5, c16 = g & 31;                                   \
            size_t go = (size_t)(b * SS + (row0) + row) * FUSED + kvh * HD + c16 * 8; \
            cp_async16((dst) + row * FPITCH + c16 * 16, (src) + go);          \
        }                                                                     \
        asm volatile("cp.async.commit_group;");                               \
    } while (0)

    LOAD_KV(sK, kh, 0);

    float o[32][4];
#pragma unroll
    for (int d = 0; d < 32; d++)
#pragma unroll
        for (int c = 0; c < 4; c++) o[d][c] = 0.f;
    float m_[2] = {-1e30f, -1e30f};
    float l_[2] = {0.f, 0.f};

    const int ra = wid * 16 + (lid & 15);
    const int rq = (lid >> 2);

    for (int kt = 0; kt <= ktmax; kt++) {
        const int k0 = kt * 64;
        asm volatile("cp.async.wait_group 0;" ::: "memory");
        __syncthreads();

        LOAD_KV(sV, vh, k0);   // overlaps S-phase

        // ----- S-phase -----
        float s[8][4];
#pragma unroll
        for (int j = 0; j < 8; j++)
#pragma unroll
            for (int c = 0; c < 4; c++) s[j][c] = 0.f;

#pragma unroll 4
        for (int kc = 0; kc < 16; kc++) {
            uint32_t a[4];
            ldsm_x4(a, sQ + (uint32_t)(ra * FPITCH + (kc * 16 + (lid >> 4) * 8) * 2));
#pragma unroll
            for (int p = 0; p < 4; p++) {
                uint32_t boff = (uint32_t)(
                    (p * 16 + ((lid >> 4) & 1) * 8 + (lid & 7)) * FPITCH
                    + (kc * 16 + ((lid >> 3) & 1) * 8) * 2);
                uint32_t bbv[4];
                ldsm_x4(bbv, sK + boff);
                mma_f16(s[2 * p],     a, &bbv[0]);
                mma_f16(s[2 * p + 1], a, &bbv[2]);
            }
        }

        __syncthreads();
        if (kt < ktmax) LOAD_KV(sK, kh, k0 + 64);   // overlaps softmax + PV

        // ----- causal mask -----
        if (k0 + 63 > q0 + wid * 16) {
#pragma unroll
            for (int j = 0; j < 8; j++)
#pragma unroll
                for (int c = 0; c < 4; c++) {
                    int col = k0 + j * 8 + (lid & 3) * 2 + (c & 1);
                    int row = q0 + wid * 16 + rq + (c >> 1) * 8;
                    if (col > row) s[j][c] = -1e30f;
                }
        }

        // ----- online softmax -----
        float alpha[2];
#pragma unroll
        for (int hh = 0; hh < 2; hh++) {
            float mx = -1e30f;
#pragma unroll
            for (int j = 0; j < 8; j++)
                mx = fmaxf(mx, fmaxf(s[j][2 * hh], s[j][2 * hh + 1]));
            mx = fmaxf(mx, __shfl_xor_sync(0xffffffffu, mx, 1));
            mx = fmaxf(mx, __shfl_xor_sync(0xffffffffu, mx, 2));
            float mnew = fmaxf(m_[hh], mx);
            alpha[hh] = __expf(m_[hh] - mnew);
            m_[hh] = mnew;
            float sum = 0.f;
#pragma unroll
            for (int j = 0; j < 8; j++) {
                float p0 = __expf(s[j][2 * hh] - mnew);
                float p1 = __expf(s[j][2 * hh + 1] - mnew);
                s[j][2 * hh] = p0;
                s[j][2 * hh + 1] = p1;
                sum += p0 + p1;
            }
            sum += __shfl_xor_sync(0xffffffffu, sum, 1);
            sum += __shfl_xor_sync(0xffffffffu, sum, 2);
            l_[hh] = l_[hh] * alpha[hh] + sum;
        }
#pragma unroll
        for (int d = 0; d < 32; d++) {
            o[d][0] *= alpha[0];
            o[d][1] *= alpha[0];
            o[d][2] *= alpha[1];
            o[d][3] *= alpha[1];
        }

        // ----- P -> fp16 fragments (registers) -----
        uint32_t p0[8], p1[8];
#pragma unroll
        for (int j = 0; j < 8; j++) {
            p0[j] = pack_h2(s[j][0], s[j][1]);
            p1[j] = pack_h2(s[j][2], s[j][3]);
        }

        if (kt < ktmax) {
            asm volatile("cp.async.wait_group 1;" ::: "memory");
        } else {
            asm volatile("cp.async.wait_group 0;" ::: "memory");
        }
        __syncthreads();

        // ----- PV phase -----
#pragma unroll
        for (int kc = 0; kc < 4; kc++) {
            uint32_t aP[4] = {p0[2 * kc], p1[2 * kc], p0[2 * kc + 1], p1[2 * kc + 1]};
#pragma unroll
            for (int dp = 0; dp < 16; dp++) {
                uint32_t voff = (uint32_t)(
                    (kc * 16 + ((lid >> 3) & 1) * 8 + (lid & 7)) * FPITCH
                    + (dp * 16 + ((lid >> 4) & 1) * 8) * 2);
                uint32_t bbv[4];
                ldsm_x4t(bbv, sV + voff);
                mma_f16(o[2 * dp],     aP, &bbv[0]);
                mma_f16(o[2 * dp + 1], aP, &bbv[2]);
            }
        }
    }

    // ----- epilogue -----
    float inv[2] = {1.f / l_[0], 1.f / l_[1]};
#pragma unroll
    for (int hh = 0; hh < 2; hh++) {
        int row = q0 + wid * 16 + rq + 8 * hh;
        size_t base = (size_t)(b * SS + row) * QDIM + h * HD;
#pragma unroll
        for (int d = 0; d < 32; d++) {
            int col = d * 8 + (lid & 3) * 2;
            float v0 = o[d][2 * hh] * inv[hh];
            float v1 = o[d][2 * hh + 1] * inv[hh];
            *(uint32_t*)(ch + base + col) = pack_h2(v0, v1);
        }
    }
#undef LOAD_KV
}

// ---------------------------------------------------------------------------
// launch
// ---------------------------------------------------------------------------
extern "C" void kernel_launch(void* const* d_in, const int* in_sizes, int n_in,
                              void* d_out, int out_size) {
    const float* x    = (const float*)d_in[0];
    const float* cosp = (const float*)d_in[2];
    const float* sinp = (const float*)d_in[3];
    const float* wq   = (const float*)d_in[4];
    const float* wk   = (const float*)d_in[5];
    const float* wv   = (const float*)d_in[6];
    const float* wo   = (const float*)d_in[7];
    const float* qg   = (const float*)d_in[8];
    const float* kg   = (const float*)d_in[9];
    float* out = (float*)d_out;

    float* pqkv;
    __half *pqkvh, *pxh, *pwf, *pwoh, *pch;
    cudaGetSymbolAddress((void**)&pqkv,  g_qkv);
    cudaGetSymbolAddress((void**)&pqkvh, g_qkvh);
    cudaGetSymbolAddress((void**)&pxh,   g_xh);
    cudaGetSymbolAddress((void**)&pwf,   g_wf);
    cudaGetSymbolAddress((void**)&pwoh,  g_woh);
    cudaGetSymbolAddress((void**)&pch,   g_ch);

    const int M = BB * SS;   // 4096

    cudaFuncSetAttribute(gemm_f16, cudaFuncAttributeMaxDynamicSharedMemorySize, GSMEM);
    cudaFuncSetAttribute(flash_f16, cudaFuncAttributeMaxDynamicSharedMemorySize,
                         FSMEM_BYTES);

    // converts (weights into fused layout)
    {
        int n4;
        n4 = (M * DIN) / 4;      cvt_f16<<<(n4 + 255) / 256, 256>>>(x,  pxh, n4);
        n4 = (QDIM * DIN) / 4;   cvt_f16<<<(n4 + 255) / 256, 256>>>(wq, pwf, n4);
        n4 = (KVDIM * DIN) / 4;  cvt_f16<<<(n4 + 255) / 256, 256>>>(
            wk, pwf + (size_t)QDIM * DIN, n4);
        n4 = (KVDIM * DIN) / 4;  cvt_f16<<<(n4 + 255) / 256, 256>>>(
            wv, pwf + (size_t)(QDIM + KVDIM) * DIN, n4);
        n4 = (DIN * QDIM) / 4;   cvt_f16<<<(n4 + 255) / 256, 256>>>(wo, pwoh, n4);
    }

    // Fused QKV projection: [M, 4096] = x @ [wq|wk|wv]^T
    gemm_f16<<<dim3(FUSED / GBN, M / GBM), 256, GSMEM>>>(pxh, pwf, pqkv, M, FUSED, DIN);

    // RMSNorm + RoPE + v-convert
    rms_rope2<<<dim3(M, 2), 256>>>(cosp, sinp, qg, kg);

    // Flash attention (q | k | v slices of fused fp16 buffer, stride FUSED)
    flash_f16<<<dim3(SS / 128, NH, BB), 256, FSMEM_BYTES>>>(
        pqkvh, pqkvh + QDIM, pqkvh + QDIM + KVDIM, pch);

    // Output projection
    gemm_f16<<<dim3(QDIM / GBN, M / GBM), 256, GSMEM>>>(pch, pwoh, out, M, QDIM, DIN);
}

// round 8
// speedup vs baseline: 1.1093x; 1.1093x over previous
#include <cuda_runtime.h>
#include <cuda_fp16.h>
#include <cstdint>
#include <math.h>

// Problem constants
#define BB   2
#define SS   2048
#define DIN  2048
#define NH   8
#define NKV  4
#define HD   256
#define QDIM  (NH*HD)    // 2048
#define KVDIM (NKV*HD)   // 1024
#define FUSED 4096       // q(2048) | k(1024) | v(1024)
#define SCALING 0.0625f
#define EPS 1e-6f

// ---------------------------------------------------------------------------
// Scratch (device globals)
// ---------------------------------------------------------------------------
__device__ float  g_qkv [(size_t)BB*SS*FUSED];   // fp32 pre-norm qkv
__device__ __half g_qkvh[(size_t)BB*SS*FUSED];   // fp16 post-norm/rope qkv
__device__ __half g_xh  [(size_t)BB*SS*DIN];
__device__ __half g_wf  [(size_t)FUSED*DIN];     // fused wq|wk|wv fp16
__device__ __half g_woh [(size_t)DIN*QDIM];
__device__ __half g_ch  [(size_t)BB*SS*QDIM];

// ---------------------------------------------------------------------------
// Helpers
// ---------------------------------------------------------------------------
__device__ __forceinline__ uint32_t smem_to_u32(const void* smem_ptr) {
    uint32_t addr;
    asm("{ .reg .u64 tmp; cvta.to.shared.u64 tmp, %1; cvt.u32.u64 %0, tmp; }"
        : "=r"(addr) : "l"(smem_ptr));
    return addr;
}
__device__ __forceinline__ void ldsm_x4(uint32_t* r, uint32_t addr) {
    asm volatile("ldmatrix.sync.aligned.m8n8.x4.shared.b16 {%0,%1,%2,%3}, [%4];"
                 : "=r"(r[0]), "=r"(r[1]), "=r"(r[2]), "=r"(r[3]) : "r"(addr));
}
__device__ __forceinline__ void ldsm_x4t(uint32_t* r, uint32_t addr) {
    asm volatile("ldmatrix.sync.aligned.m8n8.x4.trans.shared.b16 {%0,%1,%2,%3}, [%4];"
                 : "=r"(r[0]), "=r"(r[1]), "=r"(r[2]), "=r"(r[3]) : "r"(addr));
}
__device__ __forceinline__ void ldsm_x2(uint32_t& r0, uint32_t& r1, uint32_t addr) {
    asm volatile("ldmatrix.sync.aligned.m8n8.x2.shared.b16 {%0,%1}, [%2];"
                 : "=r"(r0), "=r"(r1) : "r"(addr));
}
__device__ __forceinline__ void mma_f16(float* d, const uint32_t* a, const uint32_t* b) {
    asm volatile(
        "mma.sync.aligned.m16n8k16.row.col.f32.f16.f16.f32 "
        "{%0,%1,%2,%3}, {%4,%5,%6,%7}, {%8,%9}, {%0,%1,%2,%3};"
        : "+f"(d[0]), "+f"(d[1]), "+f"(d[2]), "+f"(d[3])
        : "r"(a[0]), "r"(a[1]), "r"(a[2]), "r"(a[3]), "r"(b[0]), "r"(b[1]));
}
__device__ __forceinline__ void cp_async16(uint32_t dst, const void* src) {
    asm volatile("cp.async.cg.shared.global [%0], [%1], 16;" :: "r"(dst), "l"(src));
}
__device__ __forceinline__ uint32_t pack_h2(float x0, float x1) {
    __half2 h = __floats2half2_rn(x0, x1);
    return *(uint32_t*)&h;
}

// fp32 -> fp16 convert, vectorized by 4
__global__ void cvt_f16(const float* __restrict__ x, __half* __restrict__ out, int n4) {
    int i = blockIdx.x * blockDim.x + threadIdx.x;
    if (i >= n4) return;
    float4 v = ((const float4*)x)[i];
    uint2 r;
    r.x = pack_h2(v.x, v.y);
    r.y = pack_h2(v.z, v.w);
    ((uint2*)out)[i] = r;
}

// ---------------------------------------------------------------------------
// HMMA GEMM (NT, fp16) — R5-proven config.
// Tile 128x128, BK=32, 8 warps (2x4), warp tile 64x32, m16n8k16.
// smem: 2 stages x {A, B}, 128 rows x 80B pitch; cp.async double-buffered.
// 2 CTAs/SM.
// ---------------------------------------------------------------------------
#define HBK 32
#define HPITCH 80
#define HMAT_BYTES (128 * HPITCH)      // 10240
#define HSTAGE_BYTES (2 * HMAT_BYTES)  // 20480
#define HSMEM_BYTES (2 * HSTAGE_BYTES) // 40960

__global__ __launch_bounds__(256, 2)
void gemm_f16(const __half* __restrict__ A, const __half* __restrict__ B,
              float* __restrict__ C, int M, int N, int K) {
    extern __shared__ char smemc[];
    const uint32_t smem = smem_to_u32(smemc);
    const int tid = threadIdx.x;
    const int wid = tid >> 5;
    const int lid = tid & 31;
    const int warp_m = wid >> 2;
    const int warp_n = wid & 3;
    const int m0 = blockIdx.y * 128;
    const int n0 = blockIdx.x * 128;
    const int kchunks = K / HBK;

#define PREFETCH(cc) do {                                                     \
        const int s_ = (cc) & 1;                                              \
        const int k0_ = (cc) * HBK;                                           \
        _Pragma("unroll")                                                     \
        for (int it = 0; it < 4; it++) {                                      \
            int g = tid + 256 * it;                                           \
            int mat = g >> 9;                                                 \
            int idx = g & 511;                                                \
            int r = idx >> 2;                                                 \
            int q = idx & 3;                                                  \
            int rowg = (mat == 0 ? m0 : n0) + r;                              \
            const __half* src = (mat == 0 ? A : B) + (size_t)rowg * K + k0_ + q * 8; \
            uint32_t dst = smem + s_ * HSTAGE_BYTES + mat * HMAT_BYTES        \
                         + r * HPITCH + q * 16;                               \
            cp_async16(dst, src);                                             \
        }                                                                     \
        asm volatile("cp.async.commit_group;");                               \
    } while (0)

    float acc[4][4][4];
#pragma unroll
    for (int i = 0; i < 4; i++)
#pragma unroll
        for (int j = 0; j < 4; j++)
#pragma unroll
            for (int q = 0; q < 4; q++) acc[i][j][q] = 0.f;

    PREFETCH(0);

    for (int c = 0; c < kchunks; c++) {
        if (c + 1 < kchunks) {
            PREFETCH(c + 1);
            asm volatile("cp.async.wait_group 1;" ::: "memory");
        } else {
            asm volatile("cp.async.wait_group 0;" ::: "memory");
        }
        __syncthreads();

        const uint32_t stage = smem + (c & 1) * HSTAGE_BYTES;
        const uint32_t sA = stage;
        const uint32_t sB = stage + HMAT_BYTES;

#pragma unroll
        for (int k16 = 0; k16 < 2; k16++) {
            const int coff = k16 * 16;
            uint32_t b[4][2];
            {
                int i15 = lid & 15;
                int rb = warp_n * 32 + (i15 & 7);
                int kb = coff + ((i15 >> 3) & 1) * 8;
#pragma unroll
                for (int j = 0; j < 4; j++) {
                    uint32_t off = (uint32_t)((rb + j * 8) * HPITCH + kb * 2);
                    ldsm_x2(b[j][0], b[j][1], sB + off);
                }
            }
            uint32_t a[4][4];
            {
                int ra = warp_m * 64 + (lid & 15);
                int ka = coff + (lid >> 4) * 8;
#pragma unroll
                for (int i = 0; i < 4; i++)
                    ldsm_x4(a[i], sA + (uint32_t)((ra + i * 16) * HPITCH + ka * 2));
            }
#pragma unroll
            for (int i = 0; i < 4; i++)
#pragma unroll
                for (int j = 0; j < 4; j++)
                    mma_f16(acc[i][j], a[i], b[j]);
        }
        __syncthreads();
    }

    const int rbase = m0 + warp_m * 64 + (lid >> 2);
    const int cbase = n0 + warp_n * 32 + (lid & 3) * 2;
#pragma unroll
    for (int i = 0; i < 4; i++)
#pragma unroll
        for (int j = 0; j < 4; j++) {
            float* p0 = C + (size_t)(rbase + i * 16) * N + cbase + j * 8;
            float* p1 = C + (size_t)(rbase + i * 16 + 8) * N + cbase + j * 8;
            *(float2*)p0 = make_float2(acc[i][j][0], acc[i][j][1]);
            *(float2*)p1 = make_float2(acc[i][j][2], acc[i][j][3]);
        }
#undef PREFETCH
}

// ---------------------------------------------------------------------------
// RMSNorm + RoPE v2: warp-per-head, strided 8 elems/lane (RoPE partner is
// same-lane). heads 0-7: q, 8-11: k, 12-15: v (convert only). grid (M, 2).
// ---------------------------------------------------------------------------
__global__ void rms_rope2(const float* __restrict__ cosp,
                          const float* __restrict__ sinp,
                          const float* __restrict__ qg,
                          const float* __restrict__ kg) {
    const int bs = blockIdx.x;
    const int spos = bs & (SS - 1);
    const int wid = threadIdx.x >> 5, lane = threadIdx.x & 31;
    const int head = blockIdx.y * 8 + wid;   // 0..15

    int col0;
    if (head < 8)       col0 = head * HD;
    else if (head < 12) col0 = 2048 + (head - 8) * HD;
    else                col0 = 3072 + (head - 12) * HD;

    const float* src = g_qkv + (size_t)bs * FUSED + col0;
    __half* dst = g_qkvh + (size_t)bs * FUSED + col0;

    float v[8];
#pragma unroll
    for (int i = 0; i < 8; i++) v[i] = src[lane + 32 * i];

    if (head < 12) {
        float ssum = 0.f;
#pragma unroll
        for (int i = 0; i < 8; i++) ssum += v[i] * v[i];
#pragma unroll
        for (int off = 16; off >= 1; off >>= 1)
            ssum += __shfl_xor_sync(0xffffffffu, ssum, off);
        float rstd = rsqrtf(ssum * (1.0f / HD) + EPS);
        const float* gamma = (head < 8) ? qg : kg;
        float scale = (head < 8) ? SCALING : 1.0f;
        float xn[8];
#pragma unroll
        for (int i = 0; i < 8; i++)
            xn[i] = v[i] * rstd * (1.0f + gamma[lane + 32 * i]);
#pragma unroll
        for (int i = 0; i < 8; i++) {
            int d = lane + 32 * i;
            float rot = (i < 4) ? -xn[i + 4] : xn[i - 4];
            float o = (xn[i] * cosp[(size_t)spos * HD + d]
                     + rot * sinp[(size_t)spos * HD + d]) * scale;
            dst[d] = __float2half(o);
        }
    } else {
#pragma unroll
        for (int i = 0; i < 8; i++)
            dst[lane + 32 * i] = __float2half(v[i]);
    }
}

// ---------------------------------------------------------------------------
// Flash attention v2, fp16 HMMA. BM=128, BN=64, D=256, 256 threads (8 warps,
// warp owns 16 q-rows). Longest CTAs launched first.
// ---------------------------------------------------------------------------
#define FPITCH 528
#define FQTILE (128 * FPITCH)               // 67584
#define FKTILE (64 * FPITCH)                // 33792
#define FSMEM_BYTES (FQTILE + 2 * FKTILE)   // 135168

__global__ __launch_bounds__(256)
void flash_f16(const __half* __restrict__ qh, const __half* __restrict__ kh,
               const __half* __restrict__ vh, __half* __restrict__ ch) {
    extern __shared__ char smemc[];
    const uint32_t smem = smem_to_u32(smemc);
    const uint32_t sQ = smem;
    const uint32_t sK = smem + FQTILE;
    const uint32_t sV = smem + FQTILE + FKTILE;

    const int qb = (int)gridDim.x - 1 - (int)blockIdx.x;
    const int h = blockIdx.y, b = blockIdx.z;
    const int kvh = h >> 1;
    const int tid = threadIdx.x, wid = tid >> 5, lid = tid & 31;
    const int q0 = qb * 128;
    const int ktmax = 2 * qb + 1;

    // Q tile: 128 rows
#pragma unroll
    for (int it = 0; it < 16; it++) {
        int g = tid + 256 * it;
        int row = g >> 5, c16 = g & 31;
        size_t go = (size_t)(b * SS + q0 + row) * FUSED + h * HD + c16 * 8;
        cp_async16(sQ + row * FPITCH + c16 * 16, qh + go);
    }
    asm volatile("cp.async.commit_group;");

#define LOAD_KV(dst, src, row0) do {                                          \
        _Pragma("unroll")                                                     \
        for (int it = 0; it < 8; it++) {                                      \
            int g = tid + 256 * it;                                           \
            int row = g >> 5, c16 = g & 31;                                   \
            size_t go = (size_t)(b * SS + (row0) + row) * FUSED + kvh * HD + c16 * 8; \
            cp_async16((dst) + row * FPITCH + c16 * 16, (src) + go);          \
        }                                                                     \
        asm volatile("cp.async.commit_group;");                               \
    } while (0)

    LOAD_KV(sK, kh, 0);

    float o[32][4];
#pragma unroll
    for (int d = 0; d < 32; d++)
#pragma unroll
        for (int c = 0; c < 4; c++) o[d][c] = 0.f;
    float m_[2] = {-1e30f, -1e30f};
    float l_[2] = {0.f, 0.f};

    const int ra = wid * 16 + (lid & 15);
    const int rq = (lid >> 2);

    for (int kt = 0; kt <= ktmax; kt++) {
        const int k0 = kt * 64;
        asm volatile("cp.async.wait_group 0;" ::: "memory");
        __syncthreads();

        LOAD_KV(sV, vh, k0);   // overlaps S-phase

        // ----- S-phase -----
        float s[8][4];
#pragma unroll
        for (int j = 0; j < 8; j++)
#pragma unroll
            for (int c = 0; c < 4; c++) s[j][c] = 0.f;

#pragma unroll 4
        for (int kc = 0; kc < 16; kc++) {
            uint32_t a[4];
            ldsm_x4(a, sQ + (uint32_t)(ra * FPITCH + (kc * 16 + (lid >> 4) * 8) * 2));
#pragma unroll
            for (int p = 0; p < 4; p++) {
                uint32_t boff = (uint32_t)(
                    (p * 16 + ((lid >> 4) & 1) * 8 + (lid & 7)) * FPITCH
                    + (kc * 16 + ((lid >> 3) & 1) * 8) * 2);
                uint32_t bbv[4];
                ldsm_x4(bbv, sK + boff);
                mma_f16(s[2 * p],     a, &bbv[0]);
                mma_f16(s[2 * p + 1], a, &bbv[2]);
            }
        }

        __syncthreads();
        if (kt < ktmax) LOAD_KV(sK, kh, k0 + 64);   // overlaps softmax + PV

        // ----- causal mask -----
        if (k0 + 63 > q0 + wid * 16) {
#pragma unroll
            for (int j = 0; j < 8; j++)
#pragma unroll
                for (int c = 0; c < 4; c++) {
                    int col = k0 + j * 8 + (lid & 3) * 2 + (c & 1);
                    int row = q0 + wid * 16 + rq + (c >> 1) * 8;
                    if (col > row) s[j][c] = -1e30f;
                }
        }

        // ----- online softmax -----
        float alpha[2];
#pragma unroll
        for (int hh = 0; hh < 2; hh++) {
            float mx = -1e30f;
#pragma unroll
            for (int j = 0; j < 8; j++)
                mx = fmaxf(mx, fmaxf(s[j][2 * hh], s[j][2 * hh + 1]));
            mx = fmaxf(mx, __shfl_xor_sync(0xffffffffu, mx, 1));
            mx = fmaxf(mx, __shfl_xor_sync(0xffffffffu, mx, 2));
            float mnew = fmaxf(m_[hh], mx);
            alpha[hh] = __expf(m_[hh] - mnew);
            m_[hh] = mnew;
            float sum = 0.f;
#pragma unroll
            for (int j = 0; j < 8; j++) {
                float p0 = __expf(s[j][2 * hh] - mnew);
                float p1 = __expf(s[j][2 * hh + 1] - mnew);
                s[j][2 * hh] = p0;
                s[j][2 * hh + 1] = p1;
                sum += p0 + p1;
            }
            sum += __shfl_xor_sync(0xffffffffu, sum, 1);
            sum += __shfl_xor_sync(0xffffffffu, sum, 2);
            l_[hh] = l_[hh] * alpha[hh] + sum;
        }
#pragma unroll
        for (int d = 0; d < 32; d++) {
            o[d][0] *= alpha[0];
            o[d][1] *= alpha[0];
            o[d][2] *= alpha[1];
            o[d][3] *= alpha[1];
        }

        // ----- P -> fp16 fragments -----
        uint32_t p0[8], p1[8];
#pragma unroll
        for (int j = 0; j < 8; j++) {
            p0[j] = pack_h2(s[j][0], s[j][1]);
            p1[j] = pack_h2(s[j][2], s[j][3]);
        }

        if (kt < ktmax) {
            asm volatile("cp.async.wait_group 1;" ::: "memory");
        } else {
            asm volatile("cp.async.wait_group 0;" ::: "memory");
        }
        __syncthreads();

        // ----- PV phase -----
#pragma unroll
        for (int kc = 0; kc < 4; kc++) {
            uint32_t aP[4] = {p0[2 * kc], p1[2 * kc], p0[2 * kc + 1], p1[2 * kc + 1]};
#pragma unroll
            for (int dp = 0; dp < 16; dp++) {
                uint32_t voff = (uint32_t)(
                    (kc * 16 + ((lid >> 3) & 1) * 8 + (lid & 7)) * FPITCH
                    + (dp * 16 + ((lid >> 4) & 1) * 8) * 2);
                uint32_t bbv[4];
                ldsm_x4t(bbv, sV + voff);
                mma_f16(o[2 * dp],     aP, &bbv[0]);
                mma_f16(o[2 * dp + 1], aP, &bbv[2]);
            }
        }
    }

    // ----- epilogue -----
    float inv[2] = {1.f / l_[0], 1.f / l_[1]};
#pragma unroll
    for (int hh = 0; hh < 2; hh++) {
        int row = q0 + wid * 16 + rq + 8 * hh;
        size_t base = (size_t)(b * SS + row) * QDIM + h * HD;
#pragma unroll
        for (int d = 0; d < 32; d++) {
            int col = d * 8 + (lid & 3) * 2;
            float v0 = o[d][2 * hh] * inv[hh];
            float v1 = o[d][2 * hh + 1] * inv[hh];
            *(uint32_t*)(ch + base + col) = pack_h2(v0, v1);
        }
    }
#undef LOAD_KV
}

// ---------------------------------------------------------------------------
// launch
// ---------------------------------------------------------------------------
extern "C" void kernel_launch(void* const* d_in, const int* in_sizes, int n_in,
                              void* d_out, int out_size) {
    const float* x    = (const float*)d_in[0];
    const float* cosp = (const float*)d_in[2];
    const float* sinp = (const float*)d_in[3];
    const float* wq   = (const float*)d_in[4];
    const float* wk   = (const float*)d_in[5];
    const float* wv   = (const float*)d_in[6];
    const float* wo   = (const float*)d_in[7];
    const float* qg   = (const float*)d_in[8];
    const float* kg   = (const float*)d_in[9];
    float* out = (float*)d_out;

    float* pqkv;
    __half *pqkvh, *pxh, *pwf, *pwoh, *pch;
    cudaGetSymbolAddress((void**)&pqkv,  g_qkv);
    cudaGetSymbolAddress((void**)&pqkvh, g_qkvh);
    cudaGetSymbolAddress((void**)&pxh,   g_xh);
    cudaGetSymbolAddress((void**)&pwf,   g_wf);
    cudaGetSymbolAddress((void**)&pwoh,  g_woh);
    cudaGetSymbolAddress((void**)&pch,   g_ch);

    const int M = BB * SS;   // 4096

    cudaFuncSetAttribute(gemm_f16, cudaFuncAttributeMaxDynamicSharedMemorySize,
                         HSMEM_BYTES);
    cudaFuncSetAttribute(flash_f16, cudaFuncAttributeMaxDynamicSharedMemorySize,
                         FSMEM_BYTES);

    // converts (weights into fused layout)
    {
        int n4;
        n4 = (M * DIN) / 4;      cvt_f16<<<(n4 + 255) / 256, 256>>>(x,  pxh, n4);
        n4 = (QDIM * DIN) / 4;   cvt_f16<<<(n4 + 255) / 256, 256>>>(wq, pwf, n4);
        n4 = (KVDIM * DIN) / 4;  cvt_f16<<<(n4 + 255) / 256, 256>>>(
            wk, pwf + (size_t)QDIM * DIN, n4);
        n4 = (KVDIM * DIN) / 4;  cvt_f16<<<(n4 + 255) / 256, 256>>>(
            wv, pwf + (size_t)(QDIM + KVDIM) * DIN, n4);
        n4 = (DIN * QDIM) / 4;   cvt_f16<<<(n4 + 255) / 256, 256>>>(wo, pwoh, n4);
    }

    // Fused QKV projection: [M, 4096] = x @ [wq|wk|wv]^T
    gemm_f16<<<dim3(FUSED / 128, M / 128), 256, HSMEM_BYTES>>>(
        pxh, pwf, pqkv, M, FUSED, DIN);

    // RMSNorm + RoPE + v-convert
    rms_rope2<<<dim3(M, 2), 256>>>(cosp, sinp, qg, kg);

    // Flash attention (q | k | v slices of fused fp16 buffer, stride FUSED)
    flash_f16<<<dim3(SS / 128, NH, BB), 256, FSMEM_BYTES>>>(
        pqkvh, pqkvh + QDIM, pqkvh + QDIM + KVDIM, pch);

    // Output projection
    gemm_f16<<<dim3(QDIM / 128, M / 128), 256, HSMEM_BYTES>>>(
        pch, pwoh, out, M, QDIM, DIN);
}

// round 9
// speedup vs baseline: 1.2549x; 1.1313x over previous
#include <cuda_runtime.h>
#include <cuda_fp16.h>
#include <cstdint>
#include <math.h>

// Problem constants
#define BB   2
#define SS   2048
#define DIN  2048
#define NH   8
#define NKV  4
#define HD   256
#define QDIM  (NH*HD)    // 2048
#define KVDIM (NKV*HD)   // 1024
#define FUSED 4096       // q(2048) | k(1024) | v(1024)
#define SCALING 0.0625f
#define EPS 1e-6f

// ---------------------------------------------------------------------------
// Scratch (device globals)
// ---------------------------------------------------------------------------
__device__ float  g_qkv [(size_t)BB*SS*FUSED];   // fp32 pre-norm qkv
__device__ __half g_qkvh[(size_t)BB*SS*FUSED];   // fp16 post-norm/rope qkv
__device__ __half g_xh  [(size_t)BB*SS*DIN];
__device__ __half g_wf  [(size_t)FUSED*DIN];     // fused wq|wk|wv fp16
__device__ __half g_woh [(size_t)DIN*QDIM];
__device__ __half g_ch  [(size_t)BB*SS*QDIM];

// ---------------------------------------------------------------------------
// Helpers
// ---------------------------------------------------------------------------
__device__ __forceinline__ uint32_t smem_to_u32(const void* smem_ptr) {
    uint32_t addr;
    asm("{ .reg .u64 tmp; cvta.to.shared.u64 tmp, %1; cvt.u32.u64 %0, tmp; }"
        : "=r"(addr) : "l"(smem_ptr));
    return addr;
}
__device__ __forceinline__ void ldsm_x4(uint32_t* r, uint32_t addr) {
    asm volatile("ldmatrix.sync.aligned.m8n8.x4.shared.b16 {%0,%1,%2,%3}, [%4];"
                 : "=r"(r[0]), "=r"(r[1]), "=r"(r[2]), "=r"(r[3]) : "r"(addr));
}
__device__ __forceinline__ void ldsm_x4t(uint32_t* r, uint32_t addr) {
    asm volatile("ldmatrix.sync.aligned.m8n8.x4.trans.shared.b16 {%0,%1,%2,%3}, [%4];"
                 : "=r"(r[0]), "=r"(r[1]), "=r"(r[2]), "=r"(r[3]) : "r"(addr));
}
__device__ __forceinline__ void ldsm_x2(uint32_t& r0, uint32_t& r1, uint32_t addr) {
    asm volatile("ldmatrix.sync.aligned.m8n8.x2.shared.b16 {%0,%1}, [%2];"
                 : "=r"(r0), "=r"(r1) : "r"(addr));
}
__device__ __forceinline__ void mma_f16(float* d, const uint32_t* a, const uint32_t* b) {
    asm volatile(
        "mma.sync.aligned.m16n8k16.row.col.f32.f16.f16.f32 "
        "{%0,%1,%2,%3}, {%4,%5,%6,%7}, {%8,%9}, {%0,%1,%2,%3};"
        : "+f"(d[0]), "+f"(d[1]), "+f"(d[2]), "+f"(d[3])
        : "r"(a[0]), "r"(a[1]), "r"(a[2]), "r"(a[3]), "r"(b[0]), "r"(b[1]));
}
__device__ __forceinline__ void cp_async16(uint32_t dst, const void* src) {
    asm volatile("cp.async.cg.shared.global [%0], [%1], 16;" :: "r"(dst), "l"(src));
}
__device__ __forceinline__ uint32_t pack_h2(float x0, float x1) {
    __half2 h = __floats2half2_rn(x0, x1);
    return *(uint32_t*)&h;
}

// ---------------------------------------------------------------------------
// Merged fp32 -> fp16 convert for all 5 tensors (one launch).
// Regions in float4 units: x | wq | wk | wv | wo
// ---------------------------------------------------------------------------
#define CVT_N0 ((BB*SS*DIN)/4)          // x      2097152/... = 2097152? (8.4M/4)
#define CVT_N1 ((QDIM*DIN)/4)           // wq
#define CVT_N2 ((KVDIM*DIN)/4)          // wk
#define CVT_N3 ((KVDIM*DIN)/4)          // wv
#define CVT_N4 ((DIN*QDIM)/4)           // wo
#define CVT_TOT (CVT_N0+CVT_N1+CVT_N2+CVT_N3+CVT_N4)

__global__ void cvt_all(const float* __restrict__ x,  const float* __restrict__ wq,
                        const float* __restrict__ wk, const float* __restrict__ wv,
                        const float* __restrict__ wo) {
    int i = blockIdx.x * blockDim.x + threadIdx.x;
    if (i >= CVT_TOT) return;
    const float* src;
    __half* dst;
    int j = i;
    if (j < CVT_N0) { src = x;  dst = g_xh; }
    else if ((j -= CVT_N0) < CVT_N1) { src = wq; dst = g_wf; }
    else if ((j -= CVT_N1) < CVT_N2) { src = wk; dst = g_wf + (size_t)QDIM * DIN; }
    else if ((j -= CVT_N2) < CVT_N3) { src = wv; dst = g_wf + (size_t)(QDIM + KVDIM) * DIN; }
    else { j -= CVT_N3; src = wo; dst = g_woh; }
    float4 v = ((const float4*)src)[j];
    uint2 r;
    r.x = pack_h2(v.x, v.y);
    r.y = pack_h2(v.z, v.w);
    ((uint2*)dst)[j] = r;
}

// ---------------------------------------------------------------------------
// HMMA GEMM (NT, fp16) — R5-proven config (UNCHANGED).
// Tile 128x128, BK=32, 8 warps (2x4), warp tile 64x32, 2 CTAs/SM.
// ---------------------------------------------------------------------------
#define HBK 32
#define HPITCH 80
#define HMAT_BYTES (128 * HPITCH)      // 10240
#define HSTAGE_BYTES (2 * HMAT_BYTES)  // 20480
#define HSMEM_BYTES (2 * HSTAGE_BYTES) // 40960

__global__ __launch_bounds__(256, 2)
void gemm_f16(const __half* __restrict__ A, const __half* __restrict__ B,
              float* __restrict__ C, int M, int N, int K) {
    extern __shared__ char smemc[];
    const uint32_t smem = smem_to_u32(smemc);
    const int tid = threadIdx.x;
    const int wid = tid >> 5;
    const int lid = tid & 31;
    const int warp_m = wid >> 2;
    const int warp_n = wid & 3;
    const int m0 = blockIdx.y * 128;
    const int n0 = blockIdx.x * 128;
    const int kchunks = K / HBK;

#define PREFETCH(cc) do {                                                     \
        const int s_ = (cc) & 1;                                              \
        const int k0_ = (cc) * HBK;                                           \
        _Pragma("unroll")                                                     \
        for (int it = 0; it < 4; it++) {                                      \
            int g = tid + 256 * it;                                           \
            int mat = g >> 9;                                                 \
            int idx = g & 511;                                                \
            int r = idx >> 2;                                                 \
            int q = idx & 3;                                                  \
            int rowg = (mat == 0 ? m0 : n0) + r;                              \
            const __half* src = (mat == 0 ? A : B) + (size_t)rowg * K + k0_ + q * 8; \
            uint32_t dst = smem + s_ * HSTAGE_BYTES + mat * HMAT_BYTES        \
                         + r * HPITCH + q * 16;                               \
            cp_async16(dst, src);                                             \
        }                                                                     \
        asm volatile("cp.async.commit_group;");                               \
    } while (0)

    float acc[4][4][4];
#pragma unroll
    for (int i = 0; i < 4; i++)
#pragma unroll
        for (int j = 0; j < 4; j++)
#pragma unroll
            for (int q = 0; q < 4; q++) acc[i][j][q] = 0.f;

    PREFETCH(0);

    for (int c = 0; c < kchunks; c++) {
        if (c + 1 < kchunks) {
            PREFETCH(c + 1);
            asm volatile("cp.async.wait_group 1;" ::: "memory");
        } else {
            asm volatile("cp.async.wait_group 0;" ::: "memory");
        }
        __syncthreads();

        const uint32_t stage = smem + (c & 1) * HSTAGE_BYTES;
        const uint32_t sA = stage;
        const uint32_t sB = stage + HMAT_BYTES;

#pragma unroll
        for (int k16 = 0; k16 < 2; k16++) {
            const int coff = k16 * 16;
            uint32_t b[4][2];
            {
                int i15 = lid & 15;
                int rb = warp_n * 32 + (i15 & 7);
                int kb = coff + ((i15 >> 3) & 1) * 8;
#pragma unroll
                for (int j = 0; j < 4; j++) {
                    uint32_t off = (uint32_t)((rb + j * 8) * HPITCH + kb * 2);
                    ldsm_x2(b[j][0], b[j][1], sB + off);
                }
            }
            uint32_t a[4][4];
            {
                int ra = warp_m * 64 + (lid & 15);
                int ka = coff + (lid >> 4) * 8;
#pragma unroll
                for (int i = 0; i < 4; i++)
                    ldsm_x4(a[i], sA + (uint32_t)((ra + i * 16) * HPITCH + ka * 2));
            }
#pragma unroll
            for (int i = 0; i < 4; i++)
#pragma unroll
                for (int j = 0; j < 4; j++)
                    mma_f16(acc[i][j], a[i], b[j]);
        }
        __syncthreads();
    }

    const int rbase = m0 + warp_m * 64 + (lid >> 2);
    const int cbase = n0 + warp_n * 32 + (lid & 3) * 2;
#pragma unroll
    for (int i = 0; i < 4; i++)
#pragma unroll
        for (int j = 0; j < 4; j++) {
            float* p0 = C + (size_t)(rbase + i * 16) * N + cbase + j * 8;
            float* p1 = C + (size_t)(rbase + i * 16 + 8) * N + cbase + j * 8;
            *(float2*)p0 = make_float2(acc[i][j][0], acc[i][j][1]);
            *(float2*)p1 = make_float2(acc[i][j][2], acc[i][j][3]);
        }
#undef PREFETCH
}

// ---------------------------------------------------------------------------
// RMSNorm + RoPE v2 (unchanged).
// ---------------------------------------------------------------------------
__global__ void rms_rope2(const float* __restrict__ cosp,
                          const float* __restrict__ sinp,
                          const float* __restrict__ qg,
                          const float* __restrict__ kg) {
    const int bs = blockIdx.x;
    const int spos = bs & (SS - 1);
    const int wid = threadIdx.x >> 5, lane = threadIdx.x & 31;
    const int head = blockIdx.y * 8 + wid;   // 0..15

    int col0;
    if (head < 8)       col0 = head * HD;
    else if (head < 12) col0 = 2048 + (head - 8) * HD;
    else                col0 = 3072 + (head - 12) * HD;

    const float* src = g_qkv + (size_t)bs * FUSED + col0;
    __half* dst = g_qkvh + (size_t)bs * FUSED + col0;

    float v[8];
#pragma unroll
    for (int i = 0; i < 8; i++) v[i] = src[lane + 32 * i];

    if (head < 12) {
        float ssum = 0.f;
#pragma unroll
        for (int i = 0; i < 8; i++) ssum += v[i] * v[i];
#pragma unroll
        for (int off = 16; off >= 1; off >>= 1)
            ssum += __shfl_xor_sync(0xffffffffu, ssum, off);
        float rstd = rsqrtf(ssum * (1.0f / HD) + EPS);
        const float* gamma = (head < 8) ? qg : kg;
        float scale = (head < 8) ? SCALING : 1.0f;
        float xn[8];
#pragma unroll
        for (int i = 0; i < 8; i++)
            xn[i] = v[i] * rstd * (1.0f + gamma[lane + 32 * i]);
#pragma unroll
        for (int i = 0; i < 8; i++) {
            int d = lane + 32 * i;
            float rot = (i < 4) ? -xn[i + 4] : xn[i - 4];
            float o = (xn[i] * cosp[(size_t)spos * HD + d]
                     + rot * sinp[(size_t)spos * HD + d]) * scale;
            dst[d] = __float2half(o);
        }
    } else {
#pragma unroll
        for (int i = 0; i < 8; i++)
            dst[lane + 32 * i] = __float2half(v[i]);
    }
}

// ---------------------------------------------------------------------------
// Flash attention v3: complementary-paired q-tiles for perfect balance.
// grid (8, NH, BB) = 128 CTAs (single wave). CTA p does qb = 15-p then qb = p:
// total work = 34 k-iters for every CTA. BM=128, BN=64, 256 threads.
// ---------------------------------------------------------------------------
#define FPITCH 528
#define FQTILE (128 * FPITCH)               // 67584
#define FKTILE (64 * FPITCH)                // 33792
#define FSMEM_BYTES (FQTILE + 2 * FKTILE)   // 135168

__global__ __launch_bounds__(256)
void flash_f16(const __half* __restrict__ qh, const __half* __restrict__ kh,
               const __half* __restrict__ vh, __half* __restrict__ ch) {
    extern __shared__ char smemc[];
    const uint32_t smem = smem_to_u32(smemc);
    const uint32_t sQ = smem;
    const uint32_t sK = smem + FQTILE;
    const uint32_t sV = smem + FQTILE + FKTILE;

    const int pairIdx = blockIdx.x;          // 0..7
    const int h = blockIdx.y, b = blockIdx.z;
    const int kvh = h >> 1;
    const int tid = threadIdx.x, wid = tid >> 5, lid = tid & 31;

    const int ra = wid * 16 + (lid & 15);
    const int rq = (lid >> 2);

#define LOAD_KV(dst, src, row0) do {                                          \
        _Pragma("unroll")                                                     \
        for (int it = 0; it < 8; it++) {                                      \
            int g = tid + 256 * it;                                           \
            int row = g >> 5, c16 = g & 31;                                   \
            size_t go = (size_t)(b * SS + (row0) + row) * FUSED + kvh * HD + c16 * 8; \
            cp_async16((dst) + row * FPITCH + c16 * 16, (src) + go);          \
        }                                                                     \
        asm volatile("cp.async.commit_group;");                               \
    } while (0)

    for (int tile = 0; tile < 2; tile++) {
        const int qb = (tile == 0) ? (15 - pairIdx) : pairIdx;
        const int q0 = qb * 128;
        const int ktmax = 2 * qb + 1;

        // Q tile: 128 rows
#pragma unroll
        for (int it = 0; it < 16; it++) {
            int g = tid + 256 * it;
            int row = g >> 5, c16 = g & 31;
            size_t go = (size_t)(b * SS + q0 + row) * FUSED + h * HD + c16 * 8;
            cp_async16(sQ + row * FPITCH + c16 * 16, qh + go);
        }
        asm volatile("cp.async.commit_group;");

        LOAD_KV(sK, kh, 0);

        float o[32][4];
#pragma unroll
        for (int d = 0; d < 32; d++)
#pragma unroll
            for (int c = 0; c < 4; c++) o[d][c] = 0.f;
        float m_[2] = {-1e30f, -1e30f};
        float l_[2] = {0.f, 0.f};

        for (int kt = 0; kt <= ktmax; kt++) {
            const int k0 = kt * 64;
            asm volatile("cp.async.wait_group 0;" ::: "memory");
            __syncthreads();

            LOAD_KV(sV, vh, k0);   // overlaps S-phase

            // ----- S-phase -----
            float s[8][4];
#pragma unroll
            for (int j = 0; j < 8; j++)
#pragma unroll
                for (int c = 0; c < 4; c++) s[j][c] = 0.f;

#pragma unroll 4
            for (int kc = 0; kc < 16; kc++) {
                uint32_t a[4];
                ldsm_x4(a, sQ + (uint32_t)(ra * FPITCH + (kc * 16 + (lid >> 4) * 8) * 2));
#pragma unroll
                for (int p = 0; p < 4; p++) {
                    uint32_t boff = (uint32_t)(
                        (p * 16 + ((lid >> 4) & 1) * 8 + (lid & 7)) * FPITCH
                        + (kc * 16 + ((lid >> 3) & 1) * 8) * 2);
                    uint32_t bbv[4];
                    ldsm_x4(bbv, sK + boff);
                    mma_f16(s[2 * p],     a, &bbv[0]);
                    mma_f16(s[2 * p + 1], a, &bbv[2]);
                }
            }

            __syncthreads();
            if (kt < ktmax) LOAD_KV(sK, kh, k0 + 64);   // overlaps softmax + PV

            // ----- causal mask -----
            if (k0 + 63 > q0 + wid * 16) {
#pragma unroll
                for (int j = 0; j < 8; j++)
#pragma unroll
                    for (int c = 0; c < 4; c++) {
                        int col = k0 + j * 8 + (lid & 3) * 2 + (c & 1);
                        int row = q0 + wid * 16 + rq + (c >> 1) * 8;
                        if (col > row) s[j][c] = -1e30f;
                    }
            }

            // ----- online softmax -----
            float alpha[2];
#pragma unroll
            for (int hh = 0; hh < 2; hh++) {
                float mx = -1e30f;
#pragma unroll
                for (int j = 0; j < 8; j++)
                    mx = fmaxf(mx, fmaxf(s[j][2 * hh], s[j][2 * hh + 1]));
                mx = fmaxf(mx, __shfl_xor_sync(0xffffffffu, mx, 1));
                mx = fmaxf(mx, __shfl_xor_sync(0xffffffffu, mx, 2));
                float mnew = fmaxf(m_[hh], mx);
                alpha[hh] = __expf(m_[hh] - mnew);
                m_[hh] = mnew;
                float sum = 0.f;
#pragma unroll
                for (int j = 0; j < 8; j++) {
                    float p0 = __expf(s[j][2 * hh] - mnew);
                    float p1 = __expf(s[j][2 * hh + 1] - mnew);
                    s[j][2 * hh] = p0;
                    s[j][2 * hh + 1] = p1;
                    sum += p0 + p1;
                }
                sum += __shfl_xor_sync(0xffffffffu, sum, 1);
                sum += __shfl_xor_sync(0xffffffffu, sum, 2);
                l_[hh] = l_[hh] * alpha[hh] + sum;
            }
#pragma unroll
            for (int d = 0; d < 32; d++) {
                o[d][0] *= alpha[0];
                o[d][1] *= alpha[0];
                o[d][2] *= alpha[1];
                o[d][3] *= alpha[1];
            }

            // ----- P -> fp16 fragments -----
            uint32_t p0[8], p1[8];
#pragma unroll
            for (int j = 0; j < 8; j++) {
                p0[j] = pack_h2(s[j][0], s[j][1]);
                p1[j] = pack_h2(s[j][2], s[j][3]);
            }

            if (kt < ktmax) {
                asm volatile("cp.async.wait_group 1;" ::: "memory");
            } else {
                asm volatile("cp.async.wait_group 0;" ::: "memory");
            }
            __syncthreads();

            // ----- PV phase -----
#pragma unroll
            for (int kc = 0; kc < 4; kc++) {
                uint32_t aP[4] = {p0[2 * kc], p1[2 * kc], p0[2 * kc + 1], p1[2 * kc + 1]};
#pragma unroll
                for (int dp = 0; dp < 16; dp++) {
                    uint32_t voff = (uint32_t)(
                        (kc * 16 + ((lid >> 3) & 1) * 8 + (lid & 7)) * FPITCH
                        + (dp * 16 + ((lid >> 4) & 1) * 8) * 2);
                    uint32_t bbv[4];
                    ldsm_x4t(bbv, sV + voff);
                    mma_f16(o[2 * dp],     aP, &bbv[0]);
                    mma_f16(o[2 * dp + 1], aP, &bbv[2]);
                }
            }
        }

        // ----- epilogue -----
        float inv[2] = {1.f / l_[0], 1.f / l_[1]};
#pragma unroll
        for (int hh = 0; hh < 2; hh++) {
            int row = q0 + wid * 16 + rq + 8 * hh;
            size_t base = (size_t)(b * SS + row) * QDIM + h * HD;
#pragma unroll
            for (int d = 0; d < 32; d++) {
                int col = d * 8 + (lid & 3) * 2;
                float v0 = o[d][2 * hh] * inv[hh];
                float v1 = o[d][2 * hh + 1] * inv[hh];
                *(uint32_t*)(ch + base + col) = pack_h2(v0, v1);
            }
        }
        __syncthreads();   // all warps done before next tile's Q/K loads
    }
#undef LOAD_KV
}

// ---------------------------------------------------------------------------
// launch
// ---------------------------------------------------------------------------
extern "C" void kernel_launch(void* const* d_in, const int* in_sizes, int n_in,
                              void* d_out, int out_size) {
    const float* x    = (const float*)d_in[0];
    const float* cosp = (const float*)d_in[2];
    const float* sinp = (const float*)d_in[3];
    const float* wq   = (const float*)d_in[4];
    const float* wk   = (const float*)d_in[5];
    const float* wv   = (const float*)d_in[6];
    const float* wo   = (const float*)d_in[7];
    const float* qg   = (const float*)d_in[8];
    const float* kg   = (const float*)d_in[9];
    float* out = (float*)d_out;

    float* pqkv;
    __half *pqkvh, *pxh, *pwf, *pwoh, *pch;
    cudaGetSymbolAddress((void**)&pqkv,  g_qkv);
    cudaGetSymbolAddress((void**)&pqkvh, g_qkvh);
    cudaGetSymbolAddress((void**)&pxh,   g_xh);
    cudaGetSymbolAddress((void**)&pwf,   g_wf);
    cudaGetSymbolAddress((void**)&pwoh,  g_woh);
    cudaGetSymbolAddress((void**)&pch,   g_ch);

    const int M = BB * SS;   // 4096

    cudaFuncSetAttribute(gemm_f16, cudaFuncAttributeMaxDynamicSharedMemorySize,
                         HSMEM_BYTES);
    cudaFuncSetAttribute(flash_f16, cudaFuncAttributeMaxDynamicSharedMemorySize,
                         FSMEM_BYTES);

    // merged converts (1 launch)
    cvt_all<<<(CVT_TOT + 255) / 256, 256>>>(x, wq, wk, wv, wo);

    // Fused QKV projection: [M, 4096] = x @ [wq|wk|wv]^T
    gemm_f16<<<dim3(FUSED / 128, M / 128), 256, HSMEM_BYTES>>>(
        pxh, pwf, pqkv, M, FUSED, DIN);

    // RMSNorm + RoPE + v-convert
    rms_rope2<<<dim3(M, 2), 256>>>(cosp, sinp, qg, kg);

    // Flash attention (paired q-tiles, 128 CTAs)
    flash_f16<<<dim3(8, NH, BB), 256, FSMEM_BYTES>>>(
        pqkvh, pqkvh + QDIM, pqkvh + QDIM + KVDIM, pch);

    // Output projection
    gemm_f16<<<dim3(QDIM / 128, M / 128), 256, HSMEM_BYTES>>>(
        pch, pwoh, out, M, QDIM, DIN);
}